// round 15
// baseline (speedup 1.0000x reference)
#include <cuda_runtime.h>
#include <cuda_bf16.h>
#include <math.h>
#include <cstdint>

#define DIM 256
#define BB  4
#define TT  4096
#define ROWS (BB*TT)          // 16384

// ---------------- scratch (device globals; no allocation allowed) ----------
__device__ float g_xn  [ROWS*DIM];
__device__ float g_q   [ROWS*DIM];
__device__ float g_k   [ROWS*DIM];
__device__ float g_v   [ROWS*DIM];
__device__ float g_attn[ROWS*DIM];
__device__ float g_x2  [ROWS*DIM];
__device__ float g_hn  [ROWS*DIM];
__device__ float g_h   [ROWS*4*DIM];

// ---------------- helpers ---------------------------------------------------
__device__ __forceinline__ float f2tf32(float x) {
    uint32_t u = __float_as_uint(x);
    asm("cvt.rna.tf32.f32 %0, %0;" : "+r"(u));
    return __uint_as_float(u);
}
__device__ __forceinline__ void mma8(float* c,
                                     uint32_t a0, uint32_t a1, uint32_t a2, uint32_t a3,
                                     uint32_t b0, uint32_t b1) {
    asm volatile(
        "mma.sync.aligned.m16n8k8.row.col.f32.tf32.tf32.f32 "
        "{%0,%1,%2,%3}, {%4,%5,%6,%7}, {%8,%9}, {%0,%1,%2,%3};"
        : "+f"(c[0]), "+f"(c[1]), "+f"(c[2]), "+f"(c[3])
        : "r"(a0), "r"(a1), "r"(a2), "r"(a3), "r"(b0), "r"(b1));
}
// ldmatrix x4: loads 4 8x8 b16 matrices; used to fetch tf32 fragments.
__device__ __forceinline__ void ldsm4(uint32_t& r0, uint32_t& r1,
                                      uint32_t& r2, uint32_t& r3, uint32_t addr) {
    asm volatile("ldmatrix.sync.aligned.m8n8.x4.shared.b16 {%0,%1,%2,%3}, [%4];"
                 : "=r"(r0), "=r"(r1), "=r"(r2), "=r"(r3) : "r"(addr));
}
__device__ __forceinline__ uint32_t smem_u32(const void* p) {
    uint32_t a;
    asm("{ .reg .u64 t; cvta.to.shared.u64 t, %1; cvt.u32.u64 %0, t; }" : "=r"(a) : "l"(p));
    return a;
}
__device__ __forceinline__ void cp16(uint32_t dst, const void* src) {
    asm volatile("cp.async.cg.shared.global [%0], [%1], 16;" :: "r"(dst), "l"(src));
}
#define CP_COMMIT() asm volatile("cp.async.commit_group;" ::: "memory")
#define CP_WAIT1()  asm volatile("cp.async.wait_group 1;"  ::: "memory")
#define CP_WAIT0()  asm volatile("cp.async.wait_group 0;"  ::: "memory")

// A-frag ldsm lane geometry: 16x8 f32 tile -> rows l&15, +16B for lanes>=16
#define LM_AROW(l)  ((l) & 15)
#define LM_AOFF(l)  ((((l) >> 4) & 1) * 16)
// B-frag ldsm lane geometry (two 8x8-f32 n-tiles): rows (l&7)+(l&16?8:0), +16B if l&8
#define LM_BROW(l)  (((l) & 7) + (((l) >> 1) & 8))
#define LM_BOFF(l)  (((l) & 8) << 1)

// ---------------- RMSNorm ---------------------------------------------------
__global__ void rmsnorm_kernel(const float* __restrict__ x,
                               const float* __restrict__ w,
                               float* __restrict__ out)
{
    int row = blockIdx.x;
    int t   = threadIdx.x;
    float v = x[(size_t)row*DIM + t];
    float s = v*v;
    #pragma unroll
    for (int o = 16; o; o >>= 1) s += __shfl_xor_sync(0xffffffffu, s, o);
    __shared__ float ws[8];
    if ((t & 31) == 0) ws[t >> 5] = s;
    __syncthreads();
    float tot = ws[0]+ws[1]+ws[2]+ws[3]+ws[4]+ws[5]+ws[6]+ws[7];
    float inv = rsqrtf(tot * (1.0f/DIM) + 1e-6f);
    out[(size_t)row*DIM + t] = v * inv * w[t];
}

// ---------------- tensor-core tf32 GEMM: C = epi(A @ W^T + bias [+R]) ------
// CTA 256(M) x 128(N), 512 threads = 16 warps (4m x 4n), warp tile 64x32.
// BK=32, 3-stage cp.async. Fragment loads via ldmatrix.x4. (unchanged R11)
enum { EPI_NONE = 0, EPI_RES = 1, EPI_GELU = 2 };

#define BKC 32
#define LDK 36                         // padded row stride (floats); 144B = 9x16B
#define ATILE_B (256*LDK*4)            // 36864 bytes
#define BTILE_B (128*LDK*4)            // 18432 bytes
#define STG_B   (ATILE_B + BTILE_B)    // 55296 bytes per stage
#define GEMM_SMEM_BYTES (3*STG_B)      // 165888

template<int EPI>
__device__ __forceinline__ void
gemm_body(const float* __restrict__ A, const float* __restrict__ W,
          const float* __restrict__ bias, const float* __restrict__ R,
          float* __restrict__ C, int N, int K, float* sm)
{
    const uint32_t sb = smem_u32(sm);

    const int tid  = threadIdx.x;
    const int wid  = tid >> 5;
    const int lane = tid & 31;
    const int wm   = wid & 3;        // m-warp (rows wm*64)
    const int wn   = wid >> 2;       // n-warp (cols wn*32)
    const int g    = lane >> 2;
    const int t    = lane & 3;
    const int mBase = blockIdx.y * 256;
    const int nBase = blockIdx.x * 128;

    const int r_ld  = tid >> 3;          // 0..63
    const int c4_ld = (tid & 7) << 2;    // 0..28

    const uint32_t a_lane = (uint32_t)((wm*64 + LM_AROW(lane))*LDK*4 + LM_AOFF(lane));
    const uint32_t b_lane = (uint32_t)((wn*32 + LM_BROW(lane))*LDK*4 + LM_BOFF(lane));

    auto load_stage = [&](int s, int c) {
        const uint32_t base = sb + (uint32_t)s * STG_B;
        const float* Ag = A + (size_t)mBase * K + c * BKC;
        const float* Wg = W + (size_t)nBase * K + c * BKC;
        #pragma unroll
        for (int i = 0; i < 4; i++) {    // A: 256 rows
            int r = r_ld + i * 64;
            cp16(base + (uint32_t)(r*LDK + c4_ld)*4, Ag + (size_t)r*K + c4_ld);
        }
        #pragma unroll
        for (int i = 0; i < 2; i++) {    // W: 128 rows
            int r = r_ld + i * 64;
            cp16(base + ATILE_B + (uint32_t)(r*LDK + c4_ld)*4, Wg + (size_t)r*K + c4_ld);
        }
    };

    const int nch = K / BKC;

    load_stage(0, 0); CP_COMMIT();
    load_stage(1, 1); CP_COMMIT();

    float acc[4][4][4];
    #pragma unroll
    for (int mf = 0; mf < 4; mf++)
        #pragma unroll
        for (int nf = 0; nf < 4; nf++)
            #pragma unroll
            for (int j = 0; j < 4; j++) acc[mf][nf][j] = 0.f;

    for (int c = 0; c < nch; c++) {
        CP_WAIT1();
        __syncthreads();

        int cn = c + 2;
        if (cn < nch) load_stage(cn % 3, cn);
        CP_COMMIT();

        const uint32_t As_u = sb + (uint32_t)(c % 3) * STG_B;
        const uint32_t a_base = As_u + a_lane;
        const uint32_t b_base = As_u + ATILE_B + b_lane;

        #pragma unroll
        for (int k8 = 0; k8 < 4; k8++) {
            const uint32_t kb = (uint32_t)k8 * 32;
            uint32_t a[4][4];
            #pragma unroll
            for (int mf = 0; mf < 4; mf++)
                ldsm4(a[mf][0], a[mf][1], a[mf][2], a[mf][3],
                      a_base + (uint32_t)(mf*16*LDK*4) + kb);
            uint32_t bpair[2][4];
            ldsm4(bpair[0][0], bpair[0][1], bpair[0][2], bpair[0][3], b_base + kb);
            ldsm4(bpair[1][0], bpair[1][1], bpair[1][2], bpair[1][3],
                  b_base + (uint32_t)(16*LDK*4) + kb);
            #pragma unroll
            for (int nf = 0; nf < 4; nf++) {
                uint32_t b0 = bpair[nf >> 1][(nf & 1) * 2];
                uint32_t b1 = bpair[nf >> 1][(nf & 1) * 2 + 1];
                #pragma unroll
                for (int mf = 0; mf < 4; mf++)
                    mma8(acc[mf][nf], a[mf][0], a[mf][1], a[mf][2], a[mf][3], b0, b1);
            }
        }
    }

    // ---- epilogue ----------------------------------------------------------
    #pragma unroll
    for (int nf = 0; nf < 4; nf++) {
        const int col = nBase + wn*32 + nf*8 + 2*t;
        const float b0 = bias[col], b1 = bias[col+1];
        #pragma unroll
        for (int mf = 0; mf < 4; mf++) {
            const int row = mBase + wm*64 + mf*16 + g;
            #pragma unroll
            for (int h = 0; h < 2; h++) {       // row, row+8
                size_t off = (size_t)(row + h*8) * N + col;
                float v0 = acc[mf][nf][h*2+0] + b0;
                float v1 = acc[mf][nf][h*2+1] + b1;
                if (EPI == EPI_GELU) {
                    v0 = 0.5f*v0*(1.0f + erff(v0*0.70710678118654752f));
                    v1 = 0.5f*v1*(1.0f + erff(v1*0.70710678118654752f));
                }
                if (EPI == EPI_RES) {
                    float2 rr = *(const float2*)&R[off];
                    v0 += rr.x; v1 += rr.y;
                }
                if (EPI == EPI_NONE) {   // QKV: pre-round to tf32 so flash's
                    v0 = f2tf32(v0);     // cp.async truncation is exact
                    v1 = f2tf32(v1);
                }
                *(float2*)&C[off] = make_float2(v0, v1);
            }
        }
    }
}

template<int EPI>
__global__ void __launch_bounds__(512, 1)
gemm_one(const float* __restrict__ A, const float* __restrict__ W,
         const float* __restrict__ bias, const float* __restrict__ R,
         float* __restrict__ C, int N, int K)
{
    extern __shared__ float sm[];
    gemm_body<EPI>(A, W, bias, R, C, N, K, sm);
}

// merged QKV: blockIdx.z selects weight/bias/output
__global__ void __launch_bounds__(512, 1)
gemm_qkv(const float* __restrict__ A,
         const float* __restrict__ wq, const float* __restrict__ bq, float* __restrict__ q,
         const float* __restrict__ wk, const float* __restrict__ bk, float* __restrict__ k,
         const float* __restrict__ wv, const float* __restrict__ bv, float* __restrict__ v)
{
    extern __shared__ float sm[];
    const float* W; const float* bias; float* C;
    if (blockIdx.z == 0)      { W = wq; bias = bq; C = q; }
    else if (blockIdx.z == 1) { W = wk; bias = bk; C = k; }
    else                      { W = wv; bias = bv; C = v; }
    gemm_body<EPI_NONE>(A, W, bias, nullptr, C, DIM, DIM, sm);
}

// ---------------- flash attention: mma.sync tf32, warp grid 2m x 4n --------
// 256 threads = 8 warps. S warp tile 32x16 (mf=2, nt=2); PV 32x64 (nt=8).
// Crossbar traffic/iter: Q 4x64 + (K+V) 2x128 = 512KB (vs 640KB at 4m2n).
#define FBM 64
#define FBN 64
#define QP 260      // 1040B = 65x16B (ldsm conflict-free)
#define KP 260
#define VP 264
#define PST 68      // 272B = 17x16B (ldsm conflict-free)
#define FLASH_SMEM_BYTES ((64*QP + 64*KP + 64*VP + 64*PST + 512) * 4)  // 220160

__global__ void __launch_bounds__(256, 1)
flash_mma_kernel(const float* __restrict__ Q, const float* __restrict__ K,
                 const float* __restrict__ V, float* __restrict__ O)
{
    extern __shared__ float sm[];
    float* Qs   = sm;
    float* Ks   = Qs + 64*QP;
    float* Vs   = Ks + 64*KP;
    float* Ps   = Vs + 64*VP;
    float* pmax = Ps + 64*PST;     // [4][64]
    float* psum = pmax + 256;      // [4][64]

    const int qi  = gridDim.x - 1 - blockIdx.x;   // heavy tiles first
    const int b   = blockIdx.y;
    const int tid = threadIdx.x;
    const int wid = tid >> 5;
    const int lane = tid & 31;
    const int wm = wid & 1;        // m-warp: rows wm*32
    const int wn = wid >> 1;       // n-warp: S cols wn*16, O cols wn*64
    const int g  = lane >> 2;
    const int t  = lane & 3;

    const uint32_t ks_u = smem_u32(Ks);
    const uint32_t vs_u = smem_u32(Vs);

    // ldmatrix lane bases
    const uint32_t qa_base = smem_u32(Qs) +
        (uint32_t)((wm*32 + LM_AROW(lane))*QP*4 + LM_AOFF(lane));
    const uint32_t kb_base = ks_u +
        (uint32_t)((wn*16 + LM_BROW(lane))*KP*4 + LM_BOFF(lane));
    const uint32_t pa_base = smem_u32(Ps) +
        (uint32_t)((wm*32 + LM_AROW(lane))*PST*4 + LM_AOFF(lane));

    const float scale = 0.0625f;   // 1/sqrt(256), power of 2: preserves tf32
    const float* Qg = Q + ((size_t)b*TT + (size_t)qi*FBM) * DIM;
    const float* Kb = K + (size_t)b*TT*DIM;
    const float* Vb = V + (size_t)b*TT*DIM;

    auto cp_tile = [&](uint32_t dst_u, const float* src, int pad) {
        #pragma unroll
        for (int i = 0; i < 16; i++) {
            int f  = tid + i*256;
            int r  = f >> 6;
            int c4 = (f & 63) << 2;
            cp16(dst_u + (uint32_t)(r*pad + c4)*4, src + (size_t)r*DIM + c4);
        }
    };

    // load Q tile (values already tf32-rounded by producer GEMM)
    #pragma unroll
    for (int i = 0; i < 16; i++) {
        int f  = tid + i*256;
        int r  = f >> 6;
        int c4 = (f & 63) << 2;
        float4 qv = *(const float4*)(Qg + (size_t)r*DIM + c4);
        *(float4*)(Qs + r*QP + c4) = make_float4(
            qv.x*scale, qv.y*scale, qv.z*scale, qv.w*scale);
    }

    cp_tile(ks_u, Kb, KP); CP_COMMIT();            // K(0)
    cp_tile(vs_u, Vb, VP); CP_COMMIT();            // V(0)

    float o[2][8][4];
    #pragma unroll
    for (int mf = 0; mf < 2; mf++)
        #pragma unroll
        for (int nt = 0; nt < 8; nt++)
            #pragma unroll
            for (int j = 0; j < 4; j++) o[mf][nt][j] = 0.f;
    float mm[2][2] = {{-1e30f,-1e30f},{-1e30f,-1e30f}};
    float ll[2][2] = {{0.f,0.f},{0.f,0.f}};

    for (int kj = 0; kj <= qi; kj++) {
        if (kj > 0) {
            __syncthreads();                        // PV(kj-1) done: Vs free
            cp_tile(vs_u, Vb + (size_t)kj*FBN*DIM, VP); CP_COMMIT();  // V(kj)
        }
        CP_WAIT1();                                 // K(kj) arrived
        __syncthreads();

        // ---- S = Q K^T (mf=2 A-frags, one B-ldsm per k8) -------------------
        float s[2][2][4];
        #pragma unroll
        for (int mf = 0; mf < 2; mf++)
            #pragma unroll
            for (int nt = 0; nt < 2; nt++)
                #pragma unroll
                for (int j = 0; j < 4; j++) s[mf][nt][j] = 0.f;

        #pragma unroll 4
        for (int k8 = 0; k8 < 32; k8++) {
            const uint32_t kb = (uint32_t)k8 * 32;
            uint32_t a[2][4];
            ldsm4(a[0][0], a[0][1], a[0][2], a[0][3], qa_base + kb);
            ldsm4(a[1][0], a[1][1], a[1][2], a[1][3],
                  qa_base + (uint32_t)(16*QP*4) + kb);
            uint32_t bp[4];
            ldsm4(bp[0], bp[1], bp[2], bp[3], kb_base + kb);
            #pragma unroll
            for (int nt = 0; nt < 2; nt++) {
                uint32_t b0 = bp[nt*2], b1 = bp[nt*2+1];
                mma8(s[0][nt], a[0][0], a[0][1], a[0][2], a[0][3], b0, b1);
                mma8(s[1][nt], a[1][0], a[1][1], a[1][2], a[1][3], b0, b1);
            }
        }

        if (kj == qi) {   // causal mask on diagonal tile
            #pragma unroll
            for (int mf = 0; mf < 2; mf++) {
                const int rw = wm*32 + mf*16 + g;
                #pragma unroll
                for (int nt = 0; nt < 2; nt++) {
                    int col = wn*16 + nt*8 + 2*t;
                    if (col     > rw)     s[mf][nt][0] = -1e30f;
                    if (col + 1 > rw)     s[mf][nt][1] = -1e30f;
                    if (col     > rw + 8) s[mf][nt][2] = -1e30f;
                    if (col + 1 > rw + 8) s[mf][nt][3] = -1e30f;
                }
            }
        }

        // ---- online softmax: partial max per wn group ----------------------
        #pragma unroll
        for (int mf = 0; mf < 2; mf++) {
            float pm0 = fmaxf(fmaxf(s[mf][0][0], s[mf][0][1]),
                              fmaxf(s[mf][1][0], s[mf][1][1]));
            float pm1 = fmaxf(fmaxf(s[mf][0][2], s[mf][0][3]),
                              fmaxf(s[mf][1][2], s[mf][1][3]));
            pm0 = fmaxf(pm0, __shfl_xor_sync(0xffffffffu, pm0, 1));
            pm0 = fmaxf(pm0, __shfl_xor_sync(0xffffffffu, pm0, 2));
            pm1 = fmaxf(pm1, __shfl_xor_sync(0xffffffffu, pm1, 1));
            pm1 = fmaxf(pm1, __shfl_xor_sync(0xffffffffu, pm1, 2));
            if (t == 0) {
                const int rw = wm*32 + mf*16 + g;
                pmax[wn*64 + rw]     = pm0;
                pmax[wn*64 + rw + 8] = pm1;
            }
        }
        __syncthreads();

        float alpha[2][2];
        #pragma unroll
        for (int mf = 0; mf < 2; mf++) {
            const int rw = wm*32 + mf*16 + g;
            float nm0 = fmaxf(fmaxf(pmax[rw],       pmax[64 + rw]),
                              fmaxf(pmax[128 + rw], pmax[192 + rw]));
            float nm1 = fmaxf(fmaxf(pmax[rw+8],       pmax[64 + rw+8]),
                              fmaxf(pmax[128 + rw+8], pmax[192 + rw+8]));
            nm0 = fmaxf(mm[mf][0], nm0);
            nm1 = fmaxf(mm[mf][1], nm1);
            alpha[mf][0] = __expf(mm[mf][0] - nm0);
            alpha[mf][1] = __expf(mm[mf][1] - nm1);
            mm[mf][0] = nm0; mm[mf][1] = nm1;

            float rs0 = 0.f, rs1 = 0.f;
            #pragma unroll
            for (int nt = 0; nt < 2; nt++) {
                s[mf][nt][0] = __expf(s[mf][nt][0] - nm0);
                s[mf][nt][1] = __expf(s[mf][nt][1] - nm0);
                s[mf][nt][2] = __expf(s[mf][nt][2] - nm1);
                s[mf][nt][3] = __expf(s[mf][nt][3] - nm1);
                rs0 += s[mf][nt][0] + s[mf][nt][1];
                rs1 += s[mf][nt][2] + s[mf][nt][3];
                int col = wn*16 + nt*8 + 2*t;
                *(float2*)(Ps + rw*PST + col) =
                    make_float2(f2tf32(s[mf][nt][0]), f2tf32(s[mf][nt][1]));
                *(float2*)(Ps + (rw+8)*PST + col) =
                    make_float2(f2tf32(s[mf][nt][2]), f2tf32(s[mf][nt][3]));
            }
            rs0 += __shfl_xor_sync(0xffffffffu, rs0, 1);
            rs0 += __shfl_xor_sync(0xffffffffu, rs0, 2);
            rs1 += __shfl_xor_sync(0xffffffffu, rs1, 1);
            rs1 += __shfl_xor_sync(0xffffffffu, rs1, 2);
            if (t == 0) {
                psum[wn*64 + rw]     = rs0;
                psum[wn*64 + rw + 8] = rs1;
            }
        }

        CP_WAIT0();                                 // V(kj) arrived
        __syncthreads();                            // + P/psum staged, Ks free

        if (kj < qi) {                              // prefetch K(kj+1) over PV
            cp_tile(ks_u, Kb + (size_t)(kj+1)*FBN*DIM, KP); CP_COMMIT();
        }

        #pragma unroll
        for (int mf = 0; mf < 2; mf++) {
            const int rw = wm*32 + mf*16 + g;
            ll[mf][0] = ll[mf][0]*alpha[mf][0] + psum[rw]       + psum[64 + rw]
                                               + psum[128 + rw] + psum[192 + rw];
            ll[mf][1] = ll[mf][1]*alpha[mf][1] + psum[rw+8]       + psum[64 + rw+8]
                                               + psum[128 + rw+8] + psum[192 + rw+8];
            #pragma unroll
            for (int nt = 0; nt < 8; nt++) {
                o[mf][nt][0] *= alpha[mf][0]; o[mf][nt][1] *= alpha[mf][0];
                o[mf][nt][2] *= alpha[mf][1]; o[mf][nt][3] *= alpha[mf][1];
            }
        }

        // ---- O += P V (A via ldmatrix; V B-frags scalar, 2x duplication) ---
        #pragma unroll
        for (int k8 = 0; k8 < 8; k8++) {
            const int k0 = k8*8 + t;
            uint32_t a[2][4];
            ldsm4(a[0][0], a[0][1], a[0][2], a[0][3], pa_base + (uint32_t)k8*32);
            ldsm4(a[1][0], a[1][1], a[1][2], a[1][3],
                  pa_base + (uint32_t)(16*PST*4) + (uint32_t)k8*32);
            #pragma unroll
            for (int nt = 0; nt < 8; nt++) {
                const int nb = wn*64 + nt*8 + g;
                uint32_t b0 = __float_as_uint(Vs[k0*VP + nb]);
                uint32_t b1 = __float_as_uint(Vs[(k0+4)*VP + nb]);
                mma8(o[0][nt], a[0][0], a[0][1], a[0][2], a[0][3], b0, b1);
                mma8(o[1][nt], a[1][0], a[1][1], a[1][2], a[1][3], b0, b1);
            }
        }
    }

    // ---- write out ---------------------------------------------------------
    float* Og = O + ((size_t)b*TT + (size_t)qi*FBM) * DIM;
    #pragma unroll
    for (int mf = 0; mf < 2; mf++) {
        const int rw = wm*32 + mf*16 + g;
        float inv0 = 1.0f / ll[mf][0];
        float inv1 = 1.0f / ll[mf][1];
        #pragma unroll
        for (int nt = 0; nt < 8; nt++) {
            int col = wn*64 + nt*8 + 2*t;
            *(float2*)(Og + (size_t)rw*DIM + col) =
                make_float2(o[mf][nt][0]*inv0, o[mf][nt][1]*inv0);
            *(float2*)(Og + (size_t)(rw+8)*DIM + col) =
                make_float2(o[mf][nt][2]*inv1, o[mf][nt][3]*inv1);
        }
    }
}

// ---------------- launch ---------------------------------------------------
extern "C" void kernel_launch(void* const* d_in, const int* in_sizes, int n_in,
                              void* d_out, int out_size)
{
    const float* x           = (const float*)d_in[0];
    const float* attn_norm_w = (const float*)d_in[1];
    const float* mlp_norm_w  = (const float*)d_in[2];
    const float* wq = (const float*)d_in[3];  const float* bq = (const float*)d_in[4];
    const float* wk = (const float*)d_in[5];  const float* bk = (const float*)d_in[6];
    const float* wv = (const float*)d_in[7];  const float* bv = (const float*)d_in[8];
    const float* wo = (const float*)d_in[9];  const float* bo = (const float*)d_in[10];
    const float* w1 = (const float*)d_in[11]; const float* b1 = (const float*)d_in[12];
    const float* w2 = (const float*)d_in[13]; const float* b2 = (const float*)d_in[14];
    float* out = (float*)d_out;

    float *xn, *q, *k, *v, *attn, *x2, *hn, *h;
    cudaGetSymbolAddress((void**)&xn,   g_xn);
    cudaGetSymbolAddress((void**)&q,    g_q);
    cudaGetSymbolAddress((void**)&k,    g_k);
    cudaGetSymbolAddress((void**)&v,    g_v);
    cudaGetSymbolAddress((void**)&attn, g_attn);
    cudaGetSymbolAddress((void**)&x2,   g_x2);
    cudaGetSymbolAddress((void**)&hn,   g_hn);
    cudaGetSymbolAddress((void**)&h,    g_h);

    cudaFuncSetAttribute(flash_mma_kernel,
                         cudaFuncAttributeMaxDynamicSharedMemorySize, FLASH_SMEM_BYTES);
    cudaFuncSetAttribute(gemm_qkv,
                         cudaFuncAttributeMaxDynamicSharedMemorySize, GEMM_SMEM_BYTES);
    cudaFuncSetAttribute(gemm_one<EPI_RES>,
                         cudaFuncAttributeMaxDynamicSharedMemorySize, GEMM_SMEM_BYTES);
    cudaFuncSetAttribute(gemm_one<EPI_GELU>,
                         cudaFuncAttributeMaxDynamicSharedMemorySize, GEMM_SMEM_BYTES);

    // 1. attention-branch RMSNorm
    rmsnorm_kernel<<<ROWS, 256>>>(x, attn_norm_w, xn);

    // 2. QKV projections — one merged launch, z selects q/k/v
    gemm_qkv<<<dim3(DIM/128, ROWS/256, 3), 512, GEMM_SMEM_BYTES>>>(
        xn, wq, bq, q, wk, bk, k, wv, bv, v);

    // 3. causal attention (tensor cores, cp.async pipelined)
    flash_mma_kernel<<<dim3(TT/FBM, BB), 256, FLASH_SMEM_BYTES>>>(q, k, v, attn);

    // 4. output projection + residual
    gemm_one<EPI_RES><<<dim3(DIM/128, ROWS/256), 512, GEMM_SMEM_BYTES>>>(
        attn, wo, bo, x, x2, DIM, DIM);

    // 5. MLP-branch RMSNorm
    rmsnorm_kernel<<<ROWS, 256>>>(x2, mlp_norm_w, hn);

    // 6. MLP up + GELU
    gemm_one<EPI_GELU><<<dim3(4*DIM/128, ROWS/256), 512, GEMM_SMEM_BYTES>>>(
        hn, w1, b1, nullptr, h, 4*DIM, DIM);

    // 7. MLP down + residual -> out
    gemm_one<EPI_RES><<<dim3(DIM/128, ROWS/256), 512, GEMM_SMEM_BYTES>>>(
        h, w2, b2, x2, out, DIM, 4*DIM);
}

// round 16
// speedup vs baseline: 1.0007x; 1.0007x over previous
#include <cuda_runtime.h>
#include <cuda_bf16.h>
#include <math.h>
#include <cstdint>

#define DIM 256
#define BB  4
#define TT  4096
#define ROWS (BB*TT)          // 16384

// ---------------- scratch (device globals; no allocation allowed) ----------
__device__ float g_xn  [ROWS*DIM];
__device__ float g_q   [ROWS*DIM];
__device__ float g_k   [ROWS*DIM];
__device__ float g_v   [ROWS*DIM];
__device__ float g_attn[ROWS*DIM];
__device__ float g_x2  [ROWS*DIM];
__device__ float g_hn  [ROWS*DIM];
__device__ float g_h   [ROWS*4*DIM];

// ---------------- helpers ---------------------------------------------------
__device__ __forceinline__ float f2tf32(float x) {
    uint32_t u = __float_as_uint(x);
    asm("cvt.rna.tf32.f32 %0, %0;" : "+r"(u));
    return __uint_as_float(u);
}
__device__ __forceinline__ void mma8(float* c,
                                     uint32_t a0, uint32_t a1, uint32_t a2, uint32_t a3,
                                     uint32_t b0, uint32_t b1) {
    asm volatile(
        "mma.sync.aligned.m16n8k8.row.col.f32.tf32.tf32.f32 "
        "{%0,%1,%2,%3}, {%4,%5,%6,%7}, {%8,%9}, {%0,%1,%2,%3};"
        : "+f"(c[0]), "+f"(c[1]), "+f"(c[2]), "+f"(c[3])
        : "r"(a0), "r"(a1), "r"(a2), "r"(a3), "r"(b0), "r"(b1));
}
// ldmatrix x4: loads 4 8x8 b16 matrices; used to fetch tf32 fragments.
__device__ __forceinline__ void ldsm4(uint32_t& r0, uint32_t& r1,
                                      uint32_t& r2, uint32_t& r3, uint32_t addr) {
    asm volatile("ldmatrix.sync.aligned.m8n8.x4.shared.b16 {%0,%1,%2,%3}, [%4];"
                 : "=r"(r0), "=r"(r1), "=r"(r2), "=r"(r3) : "r"(addr));
}
__device__ __forceinline__ uint32_t smem_u32(const void* p) {
    uint32_t a;
    asm("{ .reg .u64 t; cvta.to.shared.u64 t, %1; cvt.u32.u64 %0, t; }" : "=r"(a) : "l"(p));
    return a;
}
__device__ __forceinline__ void cp16(uint32_t dst, const void* src) {
    asm volatile("cp.async.cg.shared.global [%0], [%1], 16;" :: "r"(dst), "l"(src));
}
#define CP_COMMIT() asm volatile("cp.async.commit_group;" ::: "memory")
#define CP_WAIT1()  asm volatile("cp.async.wait_group 1;"  ::: "memory")
#define CP_WAIT0()  asm volatile("cp.async.wait_group 0;"  ::: "memory")

// A-frag ldsm lane geometry: 16x8 f32 tile -> rows l&15, +16B for lanes>=16
#define LM_AROW(l)  ((l) & 15)
#define LM_AOFF(l)  ((((l) >> 4) & 1) * 16)
// B-frag ldsm lane geometry (two 8x8-f32 n-tiles): rows (l&7)+(l&16?8:0), +16B if l&8
#define LM_BROW(l)  (((l) & 7) + (((l) >> 1) & 8))
#define LM_BOFF(l)  (((l) & 8) << 1)

// ---------------- RMSNorm ---------------------------------------------------
__global__ void rmsnorm_kernel(const float* __restrict__ x,
                               const float* __restrict__ w,
                               float* __restrict__ out)
{
    int row = blockIdx.x;
    int t   = threadIdx.x;
    float v = x[(size_t)row*DIM + t];
    float s = v*v;
    #pragma unroll
    for (int o = 16; o; o >>= 1) s += __shfl_xor_sync(0xffffffffu, s, o);
    __shared__ float ws[8];
    if ((t & 31) == 0) ws[t >> 5] = s;
    __syncthreads();
    float tot = ws[0]+ws[1]+ws[2]+ws[3]+ws[4]+ws[5]+ws[6]+ws[7];
    float inv = rsqrtf(tot * (1.0f/DIM) + 1e-6f);
    out[(size_t)row*DIM + t] = v * inv * w[t];
}

// ---------------- tensor-core tf32 GEMM: C = epi(A @ W^T + bias [+R]) ------
// CTA 256(M) x 128(N), 512 threads = 16 warps (4m x 4n), warp tile 64x32.
// BK=32, 3-stage cp.async. Fragment loads via ldmatrix.x4. (unchanged R11)
enum { EPI_NONE = 0, EPI_RES = 1, EPI_GELU = 2 };

#define BKC 32
#define LDK 36                         // padded row stride (floats); 144B = 9x16B
#define ATILE_B (256*LDK*4)            // 36864 bytes
#define BTILE_B (128*LDK*4)            // 18432 bytes
#define STG_B   (ATILE_B + BTILE_B)    // 55296 bytes per stage
#define GEMM_SMEM_BYTES (3*STG_B)      // 165888

template<int EPI>
__device__ __forceinline__ void
gemm_body(const float* __restrict__ A, const float* __restrict__ W,
          const float* __restrict__ bias, const float* __restrict__ R,
          float* __restrict__ C, int N, int K, float* sm)
{
    const uint32_t sb = smem_u32(sm);

    const int tid  = threadIdx.x;
    const int wid  = tid >> 5;
    const int lane = tid & 31;
    const int wm   = wid & 3;        // m-warp (rows wm*64)
    const int wn   = wid >> 2;       // n-warp (cols wn*32)
    const int g    = lane >> 2;
    const int t    = lane & 3;
    const int mBase = blockIdx.y * 256;
    const int nBase = blockIdx.x * 128;

    const int r_ld  = tid >> 3;          // 0..63
    const int c4_ld = (tid & 7) << 2;    // 0..28

    const uint32_t a_lane = (uint32_t)((wm*64 + LM_AROW(lane))*LDK*4 + LM_AOFF(lane));
    const uint32_t b_lane = (uint32_t)((wn*32 + LM_BROW(lane))*LDK*4 + LM_BOFF(lane));

    auto load_stage = [&](int s, int c) {
        const uint32_t base = sb + (uint32_t)s * STG_B;
        const float* Ag = A + (size_t)mBase * K + c * BKC;
        const float* Wg = W + (size_t)nBase * K + c * BKC;
        #pragma unroll
        for (int i = 0; i < 4; i++) {    // A: 256 rows
            int r = r_ld + i * 64;
            cp16(base + (uint32_t)(r*LDK + c4_ld)*4, Ag + (size_t)r*K + c4_ld);
        }
        #pragma unroll
        for (int i = 0; i < 2; i++) {    // W: 128 rows
            int r = r_ld + i * 64;
            cp16(base + ATILE_B + (uint32_t)(r*LDK + c4_ld)*4, Wg + (size_t)r*K + c4_ld);
        }
    };

    const int nch = K / BKC;

    load_stage(0, 0); CP_COMMIT();
    load_stage(1, 1); CP_COMMIT();

    float acc[4][4][4];
    #pragma unroll
    for (int mf = 0; mf < 4; mf++)
        #pragma unroll
        for (int nf = 0; nf < 4; nf++)
            #pragma unroll
            for (int j = 0; j < 4; j++) acc[mf][nf][j] = 0.f;

    for (int c = 0; c < nch; c++) {
        CP_WAIT1();
        __syncthreads();

        int cn = c + 2;
        if (cn < nch) load_stage(cn % 3, cn);
        CP_COMMIT();

        const uint32_t As_u = sb + (uint32_t)(c % 3) * STG_B;
        const uint32_t a_base = As_u + a_lane;
        const uint32_t b_base = As_u + ATILE_B + b_lane;

        #pragma unroll
        for (int k8 = 0; k8 < 4; k8++) {
            const uint32_t kb = (uint32_t)k8 * 32;
            uint32_t a[4][4];
            #pragma unroll
            for (int mf = 0; mf < 4; mf++)
                ldsm4(a[mf][0], a[mf][1], a[mf][2], a[mf][3],
                      a_base + (uint32_t)(mf*16*LDK*4) + kb);
            uint32_t bpair[2][4];
            ldsm4(bpair[0][0], bpair[0][1], bpair[0][2], bpair[0][3], b_base + kb);
            ldsm4(bpair[1][0], bpair[1][1], bpair[1][2], bpair[1][3],
                  b_base + (uint32_t)(16*LDK*4) + kb);
            #pragma unroll
            for (int nf = 0; nf < 4; nf++) {
                uint32_t b0 = bpair[nf >> 1][(nf & 1) * 2];
                uint32_t b1 = bpair[nf >> 1][(nf & 1) * 2 + 1];
                #pragma unroll
                for (int mf = 0; mf < 4; mf++)
                    mma8(acc[mf][nf], a[mf][0], a[mf][1], a[mf][2], a[mf][3], b0, b1);
            }
        }
    }

    // ---- epilogue ----------------------------------------------------------
    #pragma unroll
    for (int nf = 0; nf < 4; nf++) {
        const int col = nBase + wn*32 + nf*8 + 2*t;
        const float b0 = bias[col], b1 = bias[col+1];
        #pragma unroll
        for (int mf = 0; mf < 4; mf++) {
            const int row = mBase + wm*64 + mf*16 + g;
            #pragma unroll
            for (int h = 0; h < 2; h++) {       // row, row+8
                size_t off = (size_t)(row + h*8) * N + col;
                float v0 = acc[mf][nf][h*2+0] + b0;
                float v1 = acc[mf][nf][h*2+1] + b1;
                if (EPI == EPI_GELU) {
                    v0 = 0.5f*v0*(1.0f + erff(v0*0.70710678118654752f));
                    v1 = 0.5f*v1*(1.0f + erff(v1*0.70710678118654752f));
                }
                if (EPI == EPI_RES) {
                    float2 rr = *(const float2*)&R[off];
                    v0 += rr.x; v1 += rr.y;
                }
                if (EPI == EPI_NONE) {   // QKV: pre-round to tf32 so flash's
                    v0 = f2tf32(v0);     // cp.async truncation is exact
                    v1 = f2tf32(v1);
                }
                *(float2*)&C[off] = make_float2(v0, v1);
            }
        }
    }
}

template<int EPI>
__global__ void __launch_bounds__(512, 1)
gemm_one(const float* __restrict__ A, const float* __restrict__ W,
         const float* __restrict__ bias, const float* __restrict__ R,
         float* __restrict__ C, int N, int K)
{
    extern __shared__ float sm[];
    gemm_body<EPI>(A, W, bias, R, C, N, K, sm);
}

// merged QKV: blockIdx.z selects weight/bias/output
__global__ void __launch_bounds__(512, 1)
gemm_qkv(const float* __restrict__ A,
         const float* __restrict__ wq, const float* __restrict__ bq, float* __restrict__ q,
         const float* __restrict__ wk, const float* __restrict__ bk, float* __restrict__ k,
         const float* __restrict__ wv, const float* __restrict__ bv, float* __restrict__ v)
{
    extern __shared__ float sm[];
    const float* W; const float* bias; float* C;
    if (blockIdx.z == 0)      { W = wq; bias = bq; C = q; }
    else if (blockIdx.z == 1) { W = wk; bias = bk; C = k; }
    else                      { W = wv; bias = bv; C = v; }
    gemm_body<EPI_NONE>(A, W, bias, nullptr, C, DIM, DIM, sm);
}

// ---------------- flash attention: mma.sync tf32, warp grid 2m x 4n --------
// 256 threads = 8 warps. S warp tile 32x16 (mf=2, nt=2); PV 32x64 (nt=8).
// Crossbar traffic/iter: Q 4x64 + (K+V) 2x128 = 512KB (vs 640KB at 4m2n).
#define FBM 64
#define FBN 64
#define QP 260      // 1040B = 65x16B (ldsm conflict-free)
#define KP 260
#define VP 264
#define PST 68      // 272B = 17x16B (ldsm conflict-free)
#define FLASH_SMEM_BYTES ((64*QP + 64*KP + 64*VP + 64*PST + 512) * 4)  // 220160

__global__ void __launch_bounds__(256, 1)
flash_mma_kernel(const float* __restrict__ Q, const float* __restrict__ K,
                 const float* __restrict__ V, float* __restrict__ O)
{
    extern __shared__ float sm[];
    float* Qs   = sm;
    float* Ks   = Qs + 64*QP;
    float* Vs   = Ks + 64*KP;
    float* Ps   = Vs + 64*VP;
    float* pmax = Ps + 64*PST;     // [4][64]
    float* psum = pmax + 256;      // [4][64]

    const int qi  = gridDim.x - 1 - blockIdx.x;   // heavy tiles first
    const int b   = blockIdx.y;
    const int tid = threadIdx.x;
    const int wid = tid >> 5;
    const int lane = tid & 31;
    const int wm = wid & 1;        // m-warp: rows wm*32
    const int wn = wid >> 1;       // n-warp: S cols wn*16, O cols wn*64
    const int g  = lane >> 2;
    const int t  = lane & 3;

    const uint32_t ks_u = smem_u32(Ks);
    const uint32_t vs_u = smem_u32(Vs);

    // ldmatrix lane bases
    const uint32_t qa_base = smem_u32(Qs) +
        (uint32_t)((wm*32 + LM_AROW(lane))*QP*4 + LM_AOFF(lane));
    const uint32_t kb_base = ks_u +
        (uint32_t)((wn*16 + LM_BROW(lane))*KP*4 + LM_BOFF(lane));
    const uint32_t pa_base = smem_u32(Ps) +
        (uint32_t)((wm*32 + LM_AROW(lane))*PST*4 + LM_AOFF(lane));

    const float scale = 0.0625f;   // 1/sqrt(256), power of 2: preserves tf32
    const float* Qg = Q + ((size_t)b*TT + (size_t)qi*FBM) * DIM;
    const float* Kb = K + (size_t)b*TT*DIM;
    const float* Vb = V + (size_t)b*TT*DIM;

    auto cp_tile = [&](uint32_t dst_u, const float* src, int pad) {
        #pragma unroll
        for (int i = 0; i < 16; i++) {
            int f  = tid + i*256;
            int r  = f >> 6;
            int c4 = (f & 63) << 2;
            cp16(dst_u + (uint32_t)(r*pad + c4)*4, src + (size_t)r*DIM + c4);
        }
    };

    // load Q tile (values already tf32-rounded by producer GEMM)
    #pragma unroll
    for (int i = 0; i < 16; i++) {
        int f  = tid + i*256;
        int r  = f >> 6;
        int c4 = (f & 63) << 2;
        float4 qv = *(const float4*)(Qg + (size_t)r*DIM + c4);
        *(float4*)(Qs + r*QP + c4) = make_float4(
            qv.x*scale, qv.y*scale, qv.z*scale, qv.w*scale);
    }

    cp_tile(ks_u, Kb, KP); CP_COMMIT();            // K(0)
    cp_tile(vs_u, Vb, VP); CP_COMMIT();            // V(0)

    float o[2][8][4];
    #pragma unroll
    for (int mf = 0; mf < 2; mf++)
        #pragma unroll
        for (int nt = 0; nt < 8; nt++)
            #pragma unroll
            for (int j = 0; j < 4; j++) o[mf][nt][j] = 0.f;
    float mm[2][2] = {{-1e30f,-1e30f},{-1e30f,-1e30f}};
    float ll[2][2] = {{0.f,0.f},{0.f,0.f}};

    for (int kj = 0; kj <= qi; kj++) {
        if (kj > 0) {
            __syncthreads();                        // PV(kj-1) done: Vs free
            cp_tile(vs_u, Vb + (size_t)kj*FBN*DIM, VP); CP_COMMIT();  // V(kj)
        }
        CP_WAIT1();                                 // K(kj) arrived
        __syncthreads();

        // ---- S = Q K^T (mf=2 A-frags, one B-ldsm per k8) -------------------
        float s[2][2][4];
        #pragma unroll
        for (int mf = 0; mf < 2; mf++)
            #pragma unroll
            for (int nt = 0; nt < 2; nt++)
                #pragma unroll
                for (int j = 0; j < 4; j++) s[mf][nt][j] = 0.f;

        #pragma unroll 4
        for (int k8 = 0; k8 < 32; k8++) {
            const uint32_t kb = (uint32_t)k8 * 32;
            uint32_t a[2][4];
            ldsm4(a[0][0], a[0][1], a[0][2], a[0][3], qa_base + kb);
            ldsm4(a[1][0], a[1][1], a[1][2], a[1][3],
                  qa_base + (uint32_t)(16*QP*4) + kb);
            uint32_t bp[4];
            ldsm4(bp[0], bp[1], bp[2], bp[3], kb_base + kb);
            #pragma unroll
            for (int nt = 0; nt < 2; nt++) {
                uint32_t b0 = bp[nt*2], b1 = bp[nt*2+1];
                mma8(s[0][nt], a[0][0], a[0][1], a[0][2], a[0][3], b0, b1);
                mma8(s[1][nt], a[1][0], a[1][1], a[1][2], a[1][3], b0, b1);
            }
        }

        if (kj == qi) {   // causal mask on diagonal tile
            #pragma unroll
            for (int mf = 0; mf < 2; mf++) {
                const int rw = wm*32 + mf*16 + g;
                #pragma unroll
                for (int nt = 0; nt < 2; nt++) {
                    int col = wn*16 + nt*8 + 2*t;
                    if (col     > rw)     s[mf][nt][0] = -1e30f;
                    if (col + 1 > rw)     s[mf][nt][1] = -1e30f;
                    if (col     > rw + 8) s[mf][nt][2] = -1e30f;
                    if (col + 1 > rw + 8) s[mf][nt][3] = -1e30f;
                }
            }
        }

        // ---- online softmax: partial max per wn group ----------------------
        #pragma unroll
        for (int mf = 0; mf < 2; mf++) {
            float pm0 = fmaxf(fmaxf(s[mf][0][0], s[mf][0][1]),
                              fmaxf(s[mf][1][0], s[mf][1][1]));
            float pm1 = fmaxf(fmaxf(s[mf][0][2], s[mf][0][3]),
                              fmaxf(s[mf][1][2], s[mf][1][3]));
            pm0 = fmaxf(pm0, __shfl_xor_sync(0xffffffffu, pm0, 1));
            pm0 = fmaxf(pm0, __shfl_xor_sync(0xffffffffu, pm0, 2));
            pm1 = fmaxf(pm1, __shfl_xor_sync(0xffffffffu, pm1, 1));
            pm1 = fmaxf(pm1, __shfl_xor_sync(0xffffffffu, pm1, 2));
            if (t == 0) {
                const int rw = wm*32 + mf*16 + g;
                pmax[wn*64 + rw]     = pm0;
                pmax[wn*64 + rw + 8] = pm1;
            }
        }
        __syncthreads();

        float alpha[2][2];
        #pragma unroll
        for (int mf = 0; mf < 2; mf++) {
            const int rw = wm*32 + mf*16 + g;
            float nm0 = fmaxf(fmaxf(pmax[rw],       pmax[64 + rw]),
                              fmaxf(pmax[128 + rw], pmax[192 + rw]));
            float nm1 = fmaxf(fmaxf(pmax[rw+8],       pmax[64 + rw+8]),
                              fmaxf(pmax[128 + rw+8], pmax[192 + rw+8]));
            nm0 = fmaxf(mm[mf][0], nm0);
            nm1 = fmaxf(mm[mf][1], nm1);
            alpha[mf][0] = __expf(mm[mf][0] - nm0);
            alpha[mf][1] = __expf(mm[mf][1] - nm1);
            mm[mf][0] = nm0; mm[mf][1] = nm1;

            float rs0 = 0.f, rs1 = 0.f;
            #pragma unroll
            for (int nt = 0; nt < 2; nt++) {
                s[mf][nt][0] = __expf(s[mf][nt][0] - nm0);
                s[mf][nt][1] = __expf(s[mf][nt][1] - nm0);
                s[mf][nt][2] = __expf(s[mf][nt][2] - nm1);
                s[mf][nt][3] = __expf(s[mf][nt][3] - nm1);
                rs0 += s[mf][nt][0] + s[mf][nt][1];
                rs1 += s[mf][nt][2] + s[mf][nt][3];
                int col = wn*16 + nt*8 + 2*t;
                *(float2*)(Ps + rw*PST + col) =
                    make_float2(f2tf32(s[mf][nt][0]), f2tf32(s[mf][nt][1]));
                *(float2*)(Ps + (rw+8)*PST + col) =
                    make_float2(f2tf32(s[mf][nt][2]), f2tf32(s[mf][nt][3]));
            }
            rs0 += __shfl_xor_sync(0xffffffffu, rs0, 1);
            rs0 += __shfl_xor_sync(0xffffffffu, rs0, 2);
            rs1 += __shfl_xor_sync(0xffffffffu, rs1, 1);
            rs1 += __shfl_xor_sync(0xffffffffu, rs1, 2);
            if (t == 0) {
                psum[wn*64 + rw]     = rs0;
                psum[wn*64 + rw + 8] = rs1;
            }
        }

        CP_WAIT0();                                 // V(kj) arrived
        __syncthreads();                            // + P/psum staged, Ks free

        if (kj < qi) {                              // prefetch K(kj+1) over PV
            cp_tile(ks_u, Kb + (size_t)(kj+1)*FBN*DIM, KP); CP_COMMIT();
        }

        #pragma unroll
        for (int mf = 0; mf < 2; mf++) {
            const int rw = wm*32 + mf*16 + g;
            ll[mf][0] = ll[mf][0]*alpha[mf][0] + psum[rw]       + psum[64 + rw]
                                               + psum[128 + rw] + psum[192 + rw];
            ll[mf][1] = ll[mf][1]*alpha[mf][1] + psum[rw+8]       + psum[64 + rw+8]
                                               + psum[128 + rw+8] + psum[192 + rw+8];
            #pragma unroll
            for (int nt = 0; nt < 8; nt++) {
                o[mf][nt][0] *= alpha[mf][0]; o[mf][nt][1] *= alpha[mf][0];
                o[mf][nt][2] *= alpha[mf][1]; o[mf][nt][3] *= alpha[mf][1];
            }
        }

        // ---- O += P V (A via ldmatrix; V B-frags scalar, 2x duplication) ---
        #pragma unroll
        for (int k8 = 0; k8 < 8; k8++) {
            const int k0 = k8*8 + t;
            uint32_t a[2][4];
            ldsm4(a[0][0], a[0][1], a[0][2], a[0][3], pa_base + (uint32_t)k8*32);
            ldsm4(a[1][0], a[1][1], a[1][2], a[1][3],
                  pa_base + (uint32_t)(16*PST*4) + (uint32_t)k8*32);
            #pragma unroll
            for (int nt = 0; nt < 8; nt++) {
                const int nb = wn*64 + nt*8 + g;
                uint32_t b0 = __float_as_uint(Vs[k0*VP + nb]);
                uint32_t b1 = __float_as_uint(Vs[(k0+4)*VP + nb]);
                mma8(o[0][nt], a[0][0], a[0][1], a[0][2], a[0][3], b0, b1);
                mma8(o[1][nt], a[1][0], a[1][1], a[1][2], a[1][3], b0, b1);
            }
        }
    }

    // ---- write out ---------------------------------------------------------
    float* Og = O + ((size_t)b*TT + (size_t)qi*FBM) * DIM;
    #pragma unroll
    for (int mf = 0; mf < 2; mf++) {
        const int rw = wm*32 + mf*16 + g;
        float inv0 = 1.0f / ll[mf][0];
        float inv1 = 1.0f / ll[mf][1];
        #pragma unroll
        for (int nt = 0; nt < 8; nt++) {
            int col = wn*64 + nt*8 + 2*t;
            *(float2*)(Og + (size_t)rw*DIM + col) =
                make_float2(o[mf][nt][0]*inv0, o[mf][nt][1]*inv0);
            *(float2*)(Og + (size_t)(rw+8)*DIM + col) =
                make_float2(o[mf][nt][2]*inv1, o[mf][nt][3]*inv1);
        }
    }
}

// ---------------- launch ---------------------------------------------------
extern "C" void kernel_launch(void* const* d_in, const int* in_sizes, int n_in,
                              void* d_out, int out_size)
{
    const float* x           = (const float*)d_in[0];
    const float* attn_norm_w = (const float*)d_in[1];
    const float* mlp_norm_w  = (const float*)d_in[2];
    const float* wq = (const float*)d_in[3];  const float* bq = (const float*)d_in[4];
    const float* wk = (const float*)d_in[5];  const float* bk = (const float*)d_in[6];
    const float* wv = (const float*)d_in[7];  const float* bv = (const float*)d_in[8];
    const float* wo = (const float*)d_in[9];  const float* bo = (const float*)d_in[10];
    const float* w1 = (const float*)d_in[11]; const float* b1 = (const float*)d_in[12];
    const float* w2 = (const float*)d_in[13]; const float* b2 = (const float*)d_in[14];
    float* out = (float*)d_out;

    float *xn, *q, *k, *v, *attn, *x2, *hn, *h;
    cudaGetSymbolAddress((void**)&xn,   g_xn);
    cudaGetSymbolAddress((void**)&q,    g_q);
    cudaGetSymbolAddress((void**)&k,    g_k);
    cudaGetSymbolAddress((void**)&v,    g_v);
    cudaGetSymbolAddress((void**)&attn, g_attn);
    cudaGetSymbolAddress((void**)&x2,   g_x2);
    cudaGetSymbolAddress((void**)&hn,   g_hn);
    cudaGetSymbolAddress((void**)&h,    g_h);

    cudaFuncSetAttribute(flash_mma_kernel,
                         cudaFuncAttributeMaxDynamicSharedMemorySize, FLASH_SMEM_BYTES);
    cudaFuncSetAttribute(gemm_qkv,
                         cudaFuncAttributeMaxDynamicSharedMemorySize, GEMM_SMEM_BYTES);
    cudaFuncSetAttribute(gemm_one<EPI_RES>,
                         cudaFuncAttributeMaxDynamicSharedMemorySize, GEMM_SMEM_BYTES);
    cudaFuncSetAttribute(gemm_one<EPI_GELU>,
                         cudaFuncAttributeMaxDynamicSharedMemorySize, GEMM_SMEM_BYTES);

    // 1. attention-branch RMSNorm
    rmsnorm_kernel<<<ROWS, 256>>>(x, attn_norm_w, xn);

    // 2. QKV projections — one merged launch, z selects q/k/v
    gemm_qkv<<<dim3(DIM/128, ROWS/256, 3), 512, GEMM_SMEM_BYTES>>>(
        xn, wq, bq, q, wk, bk, k, wv, bv, v);

    // 3. causal attention (tensor cores, cp.async pipelined)
    flash_mma_kernel<<<dim3(TT/FBM, BB), 256, FLASH_SMEM_BYTES>>>(q, k, v, attn);

    // 4. output projection + residual
    gemm_one<EPI_RES><<<dim3(DIM/128, ROWS/256), 512, GEMM_SMEM_BYTES>>>(
        attn, wo, bo, x, x2, DIM, DIM);

    // 5. MLP-branch RMSNorm
    rmsnorm_kernel<<<ROWS, 256>>>(x2, mlp_norm_w, hn);

    // 6. MLP up + GELU
    gemm_one<EPI_GELU><<<dim3(4*DIM/128, ROWS/256), 512, GEMM_SMEM_BYTES>>>(
        hn, w1, b1, nullptr, h, 4*DIM, DIM);

    // 7. MLP down + residual -> out
    gemm_one<EPI_RES><<<dim3(DIM/128, ROWS/256), 512, GEMM_SMEM_BYTES>>>(
        h, w2, b2, x2, out, DIM, 4*DIM);
}